// round 1
// baseline (speedup 1.0000x reference)
#include <cuda_runtime.h>
#include <math.h>

// DPLSTMCell: reference returns h_t[0] -> shape [H]=1024. Only batch row 0 is live.
// Work = two GEMVs (4096x1024 each) + 1024 elementwise LSTM ops. HBM-bound: 32MB weights.
//
// Inputs (metadata order):
//  d_in[0] x_t      (1, 8192, 1024) f32  -- only first 1024 floats used
//  d_in[1] h_prev   (1, 8192, 1024) f32  -- only first 1024 floats used
//  d_in[2] c_prev   (8192, 1024)    f32  -- only first 1024 floats used
//  d_in[3] weight_ih (4096, 1024)   f32
//  d_in[4] weight_hh (4096, 1024)   f32
//  d_in[5] bias_ih   (4096,)        f32
//  d_in[6] bias_hh   (4096,)        f32
//  d_out: 1024 f32

#define H 1024
#define D 1024

__device__ __forceinline__ float warp_reduce(float v) {
    #pragma unroll
    for (int off = 16; off > 0; off >>= 1)
        v += __shfl_xor_sync(0xFFFFFFFFu, v, off);
    return v;
}

__global__ __launch_bounds__(256, 8)
void lstm_row0_kernel(const float* __restrict__ x,
                      const float* __restrict__ h,
                      const float* __restrict__ c_prev,
                      const float* __restrict__ Wih,
                      const float* __restrict__ Whh,
                      const float* __restrict__ bih,
                      const float* __restrict__ bhh,
                      float* __restrict__ out) {
    const int n    = blockIdx.x;          // output element [0, 1024)
    const int tid  = threadIdx.x;
    const int wid  = tid >> 5;            // 0..7 : which of 8 dot products
    const int lane = tid & 31;

    // warp -> (gate, matrix): gate = wid>>1, mat = wid&1
    const int gate = wid >> 1;
    const int mat  = wid & 1;
    const int row  = gate * H + n;

    const float* __restrict__ W   = mat ? Whh : Wih;
    const float* __restrict__ vec = mat ? h   : x;

    const float4* __restrict__ w4 = reinterpret_cast<const float4*>(W + (size_t)row * D);
    const float4* __restrict__ v4 = reinterpret_cast<const float4*>(vec);

    // 1024 elems / warp = 8 float4 per lane. Front-batch all 8 LDG.128 (MLP).
    float acc = 0.0f;
    #pragma unroll
    for (int i = 0; i < 8; i++) {
        const int idx = lane + i * 32;       // float4 index within the row
        float4 wv = w4[idx];
        float4 xv = v4[idx];
        acc += wv.x * xv.x + wv.y * xv.y + wv.z * xv.z + wv.w * xv.w;
    }
    acc = warp_reduce(acc);

    __shared__ float sums[8];
    if (lane == 0) sums[wid] = acc;
    __syncthreads();

    if (tid == 0) {
        float gi = sums[0] + sums[1] + bih[n]         + bhh[n];
        float gf = sums[2] + sums[3] + bih[H + n]     + bhh[H + n];
        float gg = sums[4] + sums[5] + bih[2 * H + n] + bhh[2 * H + n];
        float go = sums[6] + sums[7] + bih[3 * H + n] + bhh[3 * H + n];

        float i_t = 1.0f / (1.0f + expf(-gi));
        float f_t = 1.0f / (1.0f + expf(-gf));
        float g_t = tanhf(gg);
        float o_t = 1.0f / (1.0f + expf(-go));

        float c_t = f_t * c_prev[n] + i_t * g_t;
        out[n] = o_t * tanhf(c_t);
    }
}

extern "C" void kernel_launch(void* const* d_in, const int* in_sizes, int n_in,
                              void* d_out, int out_size) {
    const float* x      = (const float*)d_in[0];
    const float* h      = (const float*)d_in[1];
    const float* c_prev = (const float*)d_in[2];
    const float* Wih    = (const float*)d_in[3];
    const float* Whh    = (const float*)d_in[4];
    const float* bih    = (const float*)d_in[5];
    const float* bhh    = (const float*)d_in[6];
    float* out = (float*)d_out;

    lstm_row0_kernel<<<H, 256>>>(x, h, c_prev, Wih, Whh, bih, bhh, out);
}